// round 1
// baseline (speedup 1.0000x reference)
#include <cuda_runtime.h>
#include <cstdint>

#define H 64
#define NMAX 100096   // padded max node count (actual N = 100000)

// ---------------- static scratch (allocation-free) ----------------
__device__ float4 g_x   [NMAX * H / 4];   // gathered node features  [N,64]
__device__ float4 g_agg1[NMAX * H / 4];   // layer-1 neighbor sums
__device__ float4 g_agg2[NMAX * H / 4];   // layer-2 neighbor sums
__device__ float4 g_h1  [NMAX * H / 4];   // layer-1 output
__device__ float4 g_h2  [NMAX * H / 4];   // layer-2 output
__device__ float  g_deg [NMAX];
__device__ float  g_inv [NMAX];

// ---------------- prologue kernels ----------------
__global__ void zero_kernel(int n) {
    unsigned t = blockIdx.x * blockDim.x + threadIdx.x;
    unsigned total4 = (unsigned)n * (H / 4);
    if (t < total4) {
        float4 z = make_float4(0.f, 0.f, 0.f, 0.f);
        g_agg1[t] = z;
        g_agg2[t] = z;
    }
    if (t < (unsigned)n) g_deg[t] = 0.f;
}

__global__ void gather_kernel(const float4* __restrict__ emb,
                              const int* __restrict__ nid, int n) {
    unsigned t = blockIdx.x * blockDim.x + threadIdx.x;
    unsigned i = t >> 4, q = t & 15;
    if (i >= (unsigned)n) return;
    int src = nid[i];
    g_x[(size_t)i * 16 + q] = emb[(size_t)src * 16 + q];
}

__global__ void deg_kernel(const int* __restrict__ ei, int E) {
    unsigned e = blockIdx.x * blockDim.x + threadIdx.x;
    if (e >= (unsigned)E) return;
    atomicAdd(&g_deg[ei[E + e]], 1.0f);
}

__global__ void inv_kernel(int n) {
    unsigned i = blockIdx.x * blockDim.x + threadIdx.x;
    if (i < (unsigned)n) g_inv[i] = 1.0f / fmaxf(g_deg[i], 1.0f);
}

// ---------------- scatter-mean aggregation (sum part) ----------------
// 16 threads per edge, float4 each; vectorized REDG (no return) for the scatter.
template <int LAYER>
__global__ void agg_kernel(const int* __restrict__ ei, int E) {
    unsigned t = blockIdx.x * blockDim.x + threadIdx.x;
    unsigned e = t >> 4, q = t & 15;
    if (e >= (unsigned)E) return;
    int s = __ldg(ei + e);
    int d = __ldg(ei + E + e);
    const float4* feat = (LAYER == 1) ? g_x : g_h1;
    float4 v = feat[(size_t)s * 16 + q];
    float* agg = (LAYER == 1) ? (float*)g_agg1 : (float*)g_agg2;
    float* p = agg + (size_t)d * H + q * 4;
    asm volatile("red.global.add.v4.f32 [%0], {%1,%2,%3,%4};"
                 :: "l"(p), "f"(v.x), "f"(v.y), "f"(v.z), "f"(v.w)
                 : "memory");
}

// ---------------- fused SAGE layer: out = [relu]((agg*inv) @ Wl^T + x @ Wr^T + b) ----
// Warp per node. W4[h][l] packs (Wl[2l][h], Wl[2l+1][h], Wr[2l][h], Wr[2l+1][h]).
// Inner loop: LDS.64 broadcast (agg[h], x[h]) + LDS.128 + 4 FFMA -> FFMA-bound.
template <int LAYER>
__global__ __launch_bounds__(256) void gemm_kernel(const float* __restrict__ Wl,
                                                   const float* __restrict__ Wr,
                                                   const float* __restrict__ bias,
                                                   int n) {
    __shared__ float4 W4[64 * 32];
    __shared__ float2 rowbuf[8][64];

    int tid = threadIdx.x;
    for (int i = tid; i < 64 * 32; i += 256) {
        int h = i >> 5, l = i & 31;
        W4[i] = make_float4(Wl[(2 * l) * 64 + h], Wl[(2 * l + 1) * 64 + h],
                            Wr[(2 * l) * 64 + h], Wr[(2 * l + 1) * 64 + h]);
    }
    __syncthreads();

    int warp = tid >> 5, lane = tid & 31;
    float2 b2 = make_float2(bias[2 * lane], bias[2 * lane + 1]);

    const float2* aggv = (const float2*)((LAYER == 1) ? g_agg1 : g_agg2);
    const float2* xinv = (const float2*)((LAYER == 1) ? g_x : g_h1);
    float2* outv = (float2*)((LAYER == 1) ? g_h1 : g_h2);

    int warps_total = gridDim.x * 8;
    for (int node = blockIdx.x * 8 + warp; node < n; node += warps_total) {
        float inv = g_inv[node];
        float2 a2 = aggv[(size_t)node * 32 + lane];
        float2 x2 = xinv[(size_t)node * 32 + lane];
        rowbuf[warp][2 * lane]     = make_float2(a2.x * inv, x2.x);
        rowbuf[warp][2 * lane + 1] = make_float2(a2.y * inv, x2.y);
        __syncwarp();

        float2 acc = b2;
#pragma unroll
        for (int h = 0; h < 64; h++) {
            float2 ax = rowbuf[warp][h];
            float4 w  = W4[h * 32 + lane];
            acc.x += ax.x * w.x + ax.y * w.z;
            acc.y += ax.x * w.y + ax.y * w.w;
        }
        if (LAYER == 1) {
            acc.x = fmaxf(acc.x, 0.f);
            acc.y = fmaxf(acc.y, 0.f);
        }
        outv[(size_t)node * 32 + lane] = acc;
        __syncwarp();  // protect rowbuf before next iteration's restaging
    }
}

// ---------------- edge-dot classifier: out[e] = dot(h2[src], h2[dst]) -------
__global__ void edge_dot_kernel(const int* __restrict__ ei,
                                float* __restrict__ out, int E) {
    unsigned t = blockIdx.x * blockDim.x + threadIdx.x;
    unsigned e = t >> 3, q = t & 7;
    if (e >= (unsigned)E) return;
    int s = __ldg(ei + e);
    int d = __ldg(ei + E + e);
    const float4* hs = g_h2 + (size_t)s * 16;
    const float4* hd = g_h2 + (size_t)d * 16;
    float4 a0 = hs[2 * q], a1 = hs[2 * q + 1];
    float4 c0 = hd[2 * q], c1 = hd[2 * q + 1];
    float sum = a0.x * c0.x + a0.y * c0.y + a0.z * c0.z + a0.w * c0.w
              + a1.x * c1.x + a1.y * c1.y + a1.z * c1.z + a1.w * c1.w;
    sum += __shfl_xor_sync(0xffffffffu, sum, 1);
    sum += __shfl_xor_sync(0xffffffffu, sum, 2);
    sum += __shfl_xor_sync(0xffffffffu, sum, 4);
    if (q == 0) out[e] = sum;
}

// ---------------- launch ----------------
extern "C" void kernel_launch(void* const* d_in, const int* in_sizes, int n_in,
                              void* d_out, int out_size) {
    const float* emb = (const float*)d_in[0];
    const float* Wl1 = (const float*)d_in[1];
    const float* Wr1 = (const float*)d_in[2];
    const float* b1  = (const float*)d_in[3];
    const float* Wl2 = (const float*)d_in[4];
    const float* Wr2 = (const float*)d_in[5];
    const float* b2  = (const float*)d_in[6];
    const int*   nid = (const int*)d_in[7];
    const int*   ei  = (const int*)d_in[8];
    float* out = (float*)d_out;

    int n = in_sizes[0] / H;       // 100000
    int E = in_sizes[8] / 2;       // 1600000

    unsigned thr = 256;
    unsigned zb  = ((unsigned)n * 16 + thr - 1) / thr;
    unsigned gb  = ((unsigned)n * 16 + thr - 1) / thr;
    unsigned eb  = ((unsigned)E + thr - 1) / thr;
    unsigned nb  = ((unsigned)n + thr - 1) / thr;
    unsigned ab  = ((unsigned)E * 16 + thr - 1) / thr;
    unsigned db  = ((unsigned)E * 8 + thr - 1) / thr;

    zero_kernel<<<zb, thr>>>(n);
    gather_kernel<<<gb, thr>>>((const float4*)emb, nid, n);
    deg_kernel<<<eb, thr>>>(ei, E);
    inv_kernel<<<nb, thr>>>(n);

    agg_kernel<1><<<ab, thr>>>(ei, E);
    gemm_kernel<1><<<592, thr>>>(Wl1, Wr1, b1, n);

    agg_kernel<2><<<ab, thr>>>(ei, E);
    gemm_kernel<2><<<592, thr>>>(Wl2, Wr2, b2, n);

    edge_dot_kernel<<<db, thr>>>(ei, out, E);
}